// round 2
// baseline (speedup 1.0000x reference)
#include <cuda_runtime.h>

// Problem constants (fixed shapes per reference)
#define NB   16384        // batch
#define DD   512          // D
#define N1C  1024         // 2D  (gemm1 output cols)
#define K1C  512          // gemm1 K (t folded into bias)
#define N2C  512          // gemm2 output cols
#define K2C  1024         // gemm2 K (t folded into bias)

// Scratch in device globals (no allocations allowed)
__device__ float g_W1p[N1C * K1C];                 // 2 MB, dense repack of W1[:, :512]
__device__ float g_W2p[N2C * K2C];                 // 2 MB, dense repack of W2[:, :1024]
__device__ float g_beff1[N1C];                     // b1 + t*W1[:,512]
__device__ float g_beff2[N2C];                     // b2 + t*W2[:,1024]
__device__ float g_c[N1C];                         // c[j] = sum_k W2[k,j]*W1[j,k]
__device__ float g_h[(long long)NB * N1C];         // 64 MB relu activations

// Packed fp32x2 FMA (Blackwell sm_10x): d = a*b + c elementwise on 2 lanes
#define FMA_F32X2(d, a, b, c) \
    asm("fma.rn.f32x2 %0, %1, %2, %3;" : "=l"(d) : "l"(a), "l"(b), "l"(c))

// ---------------------------------------------------------------------------
// Prep: repack weights to dense aligned layout
// ---------------------------------------------------------------------------
__global__ void prep_pack(const float* __restrict__ W1, const float* __restrict__ W2) {
    int idx = blockIdx.x * 256 + threadIdx.x;
    if (idx < N1C * K1C) {
        int n = idx >> 9;          // /512
        int k = idx & 511;
        g_W1p[idx] = W1[n * 513 + k];
    } else {
        int j = idx - N1C * K1C;
        if (j < N2C * K2C) {
            int n = j >> 10;       // /1024
            int k = j & 1023;
            g_W2p[j] = W2[n * 1025 + k];
        }
    }
}

// Prep: c vector + effective biases (t folded)
__global__ void prep_cbias(const float* __restrict__ t,
                           const float* __restrict__ W1, const float* __restrict__ b1,
                           const float* __restrict__ W2, const float* __restrict__ b2) {
    int j = blockIdx.x * 256 + threadIdx.x;
    float t0 = t[0];
    if (j < N1C) {
        const float* w1row = W1 + (size_t)j * 513;
        float s = 0.f;
        #pragma unroll 4
        for (int k = 0; k < K1C; k++)
            s += W2[(size_t)k * 1025 + j] * w1row[k];
        g_c[j] = s;
        g_beff1[j] = b1[j] + t0 * w1row[512];
    }
    if (j < N2C) {
        g_beff2[j] = b2[j] + t0 * W2[(size_t)j * 1025 + 1024];
    }
}

// ---------------------------------------------------------------------------
// Fused SGEMM (NT): C = A@B^T + bias, inner loop on packed fma.rn.f32x2.
// PHASE 1: A = z,   B = W1p, out = relu(.) -> g_h
// PHASE 2: A = g_h, B = W2p, out = dz -> d_out; also trace (mask@c) -> dlogp
// Tile: 128x128x8, 256 threads, 8x8 outputs/thread held as 8x4 f32x2 pairs.
// A is stored duplicated in smem so broadcast pairs {a,a} come from one LDS.64.
// ---------------------------------------------------------------------------
template<int PHASE>
__global__ void __launch_bounds__(256, 2)
sgemm_kernel(const float* __restrict__ Aparam, float* __restrict__ Outparam) {
    constexpr int K   = (PHASE == 1) ? K1C : K2C;
    constexpr int LDA = K;
    constexpr int LDB = K;
    constexpr int LDC = (PHASE == 1) ? N1C : N2C;

    const float* A  = (PHASE == 1) ? Aparam : (const float*)g_h;
    const float* Bw = (PHASE == 1) ? (const float*)g_W1p : (const float*)g_W2p;
    float* outp     = (PHASE == 1) ? (float*)g_h : Outparam;

    __shared__ float As2[8][128][2];   // duplicated A: [k][m][{a,a}]  (8 KB)
    __shared__ float Bs[8][128];       // [k][n]                       (4 KB)

    const int tid  = threadIdx.x;
    const int m0   = blockIdx.y * 128;
    const int n0   = blockIdx.x * 128;

    // loader mapping: 2 threads per row, each one float4 along K
    const int lrow = tid >> 1;              // 0..127
    const int lk4  = (tid & 1) << 2;        // 0 or 4

    const float* Ap = A  + (size_t)(m0 + lrow) * LDA + lk4;
    const float* Bp = Bw + (size_t)(n0 + lrow) * LDB + lk4;

    const int tx = tid & 15;
    const int ty = tid >> 4;

    // 8 rows x 4 column-pairs of packed accumulators (=64 fp32 outputs)
    unsigned long long accP[8][4];
    #pragma unroll
    for (int i = 0; i < 8; i++)
        #pragma unroll
        for (int j = 0; j < 4; j++) accP[i][j] = 0ULL;

    // trace accumulator (PHASE 2, n-tile 0 only): mask(h) @ c along K
    float tr = 0.f;
    const bool do_trace = (PHASE == 2) && (blockIdx.x == 0);

    float4 av = *(const float4*)Ap;
    float4 bv = *(const float4*)Bp;

    for (int k0 = 0; k0 < K; k0 += 8) {
        // store A duplicated ({a,a} pairs), B plain
        #pragma unroll
        for (int w = 0; w < 4; w++) {
            float v = (&av.x)[w];
            *(float2*)&As2[lk4 + w][lrow][0] = make_float2(v, v);
        }
        Bs[lk4 + 0][lrow] = bv.x;
        Bs[lk4 + 1][lrow] = bv.y;
        Bs[lk4 + 2][lrow] = bv.z;
        Bs[lk4 + 3][lrow] = bv.w;

        if (do_trace) {
            const float4 cv = *(const float4*)(g_c + k0 + lk4);
            tr += (av.x > 0.f) ? cv.x : 0.f;
            tr += (av.y > 0.f) ? cv.y : 0.f;
            tr += (av.z > 0.f) ? cv.z : 0.f;
            tr += (av.w > 0.f) ? cv.w : 0.f;
        }

        __syncthreads();

        if (k0 + 8 < K) {   // prefetch next tiles into registers
            av = *(const float4*)(Ap + k0 + 8);
            bv = *(const float4*)(Bp + k0 + 8);
        }

        #pragma unroll
        for (int kk = 0; kk < 8; kk++) {
            // a broadcast pairs: rows ty*4..+3 and ty*4+64..+67
            ulonglong2 a01 = *(const ulonglong2*)&As2[kk][ty * 4 + 0][0];
            ulonglong2 a23 = *(const ulonglong2*)&As2[kk][ty * 4 + 2][0];
            ulonglong2 a45 = *(const ulonglong2*)&As2[kk][ty * 4 + 64][0];
            ulonglong2 a67 = *(const ulonglong2*)&As2[kk][ty * 4 + 66][0];
            unsigned long long aP[8] = {a01.x, a01.y, a23.x, a23.y,
                                        a45.x, a45.y, a67.x, a67.y};
            // b pairs come straight out of Bs float4s
            ulonglong2 b03 = *(const ulonglong2*)&Bs[kk][tx * 4];
            ulonglong2 b47 = *(const ulonglong2*)&Bs[kk][tx * 4 + 64];
            unsigned long long bP[4] = {b03.x, b03.y, b47.x, b47.y};

            #pragma unroll
            for (int i = 0; i < 8; i++)
                #pragma unroll
                for (int j = 0; j < 4; j++)
                    FMA_F32X2(accP[i][j], aP[i], bP[j], accP[i][j]);
        }
        __syncthreads();
    }

    // ---------------- epilogue ----------------
    const float* bias = (PHASE == 1) ? g_beff1 : g_beff2;
    const float4 be0 = *(const float4*)(bias + n0 + tx * 4);
    const float4 be1 = *(const float4*)(bias + n0 + 64 + tx * 4);
    const float beb[8] = {be0.x, be0.y, be0.z, be0.w, be1.x, be1.y, be1.z, be1.w};

    #pragma unroll
    for (int i = 0; i < 8; i++) {
        int m = m0 + ty * 4 + (i & 3) + ((i >= 4) ? 64 : 0);
        float v[8];
        #pragma unroll
        for (int j = 0; j < 4; j++) {
            float2 p = *(float2*)&accP[i][j];
            v[2 * j + 0] = p.x + beb[2 * j + 0];
            v[2 * j + 1] = p.y + beb[2 * j + 1];
        }
        if (PHASE == 1) {
            #pragma unroll
            for (int j = 0; j < 8; j++) v[j] = fmaxf(v[j], 0.f);
        }
        float* cp = outp + (size_t)m * LDC + n0 + tx * 4;
        *(float4*)cp        = make_float4(v[0], v[1], v[2], v[3]);
        *(float4*)(cp + 64) = make_float4(v[4], v[5], v[6], v[7]);
    }

    if (do_trace) {
        // each row's trace is split across its two loader threads (k%8 in
        // 0..3 vs 4..7); combine with a fixed-order shfl -> deterministic
        float tro = __shfl_xor_sync(0xffffffffu, tr, 1);
        if ((tid & 1) == 0) {
            float tot = tr + tro;
            outp[(size_t)NB * N2C + (m0 + lrow)] = -tot;
        }
    }
}

// ---------------------------------------------------------------------------
extern "C" void kernel_launch(void* const* d_in, const int* in_sizes, int n_in,
                              void* d_out, int out_size) {
    const float* t  = (const float*)d_in[0];
    const float* z  = (const float*)d_in[1];
    // d_in[2] = logp_z (all zeros; unused by the math)
    const float* W1 = (const float*)d_in[3];
    const float* b1 = (const float*)d_in[4];
    const float* W2 = (const float*)d_in[5];
    const float* b2 = (const float*)d_in[6];
    float* out = (float*)d_out;   // layout: dz (NB*512) then dlogp (NB)

    // Prep (cheap)
    prep_pack<<<(N1C * K1C + N2C * K2C + 255) / 256, 256>>>(W1, W2);
    prep_cbias<<<4, 256>>>(t, W1, b1, W2, b2);

    // GEMM1: h = relu(z @ W1p^T + beff1) -> g_h
    {
        dim3 grid(N1C / 128, NB / 128);   // (8, 128)
        sgemm_kernel<1><<<grid, 256>>>(z, nullptr);
    }
    // GEMM2: dz = h @ W2p^T + beff2 -> out; dlogp = -(mask@c) -> out tail
    {
        dim3 grid(N2C / 128, NB / 128);   // (4, 128)
        sgemm_kernel<2><<<grid, 256>>>(nullptr, out);
    }
}